// round 17
// baseline (speedup 1.0000x reference)
#include <cuda_runtime.h>
#include <cuda_bf16.h>
#include <cuda_fp16.h>
#include <cstdint>

// Problem constants
#define NMAX 100000
#define EMAX 800000
#define HPAD 100096   // NMAX rounded up to 128 (tile padding)
#define BCAP 64       // bucket capacity per node (in-deg ~Poisson(8); P(>63)~1e-40)

// Scratch (no allocation allowed -> __device__ globals)
// g_cnt relies on zero-at-entry: zero at module load, re-zeroed by
// k_edge128_mean (last consumer) every call -> invariant holds per replay.
// g_bucket padded +16: edge kernels prefetch one quad past deg (stale/zero
// entries are valid node indices; score-masked via k<rem).
__device__ float g_xl[NMAX * 128];     // fp16 xl (half2) buffers
__device__ float g_xr[NMAX * 128];     // fp32 xr
__device__ __align__(16) unsigned char g_hhi[HPAD * 128];  // h bf16-hi image (swizzled)
__device__ __align__(16) unsigned char g_hlo[HPAD * 128];  // h bf16-lo image (swizzled)
__device__ int   g_cnt[NMAX];
__device__ __align__(16) int g_bucket[NMAX * BCAP + 16];
// bf16 [n=128][k=64] W images (XOR-swizzled): 0:[W1l|W1r] 1:[W2l|W2r] 2:W3l 3:W3r
__device__ __align__(16) unsigned char g_wimg_hi[4][16384];
__device__ __align__(16) unsigned char g_wimg_lo[4][16384];

// ---------------------------------------------------------------------------
// helpers
// ---------------------------------------------------------------------------
__device__ __forceinline__ uint32_t smem_u32(const void* p) {
    uint32_t a;
    asm("{ .reg .u64 t; cvta.to.shared.u64 t, %1; cvt.u32.u64 %0, t; }" : "=r"(a) : "l"(p));
    return a;
}
__device__ __forceinline__ void bf16_split(float v, uint16_t& hi, uint16_t& lo) {
    __nv_bfloat16 h = __float2bfloat16(v);
    float residual = v - __bfloat162float(h);
    __nv_bfloat16 l = __float2bfloat16(residual);
    hi = *(uint16_t*)&h;
    lo = *(uint16_t*)&l;
}
__device__ __forceinline__ void ldm_x4(uint32_t (&r)[4], uint32_t addr) {
    asm volatile("ldmatrix.sync.aligned.m8n8.x4.shared.b16 {%0,%1,%2,%3}, [%4];"
                 : "=r"(r[0]), "=r"(r[1]), "=r"(r[2]), "=r"(r[3]) : "r"(addr));
}
__device__ __forceinline__ void mma_bf16(float (&d)[4], const uint32_t (&a)[4],
                                         uint32_t b0, uint32_t b1) {
    asm volatile(
        "mma.sync.aligned.m16n8k16.row.col.f32.bf16.bf16.f32 "
        "{%0,%1,%2,%3}, {%4,%5,%6,%7}, {%8,%9}, {%0,%1,%2,%3};"
        : "+f"(d[0]), "+f"(d[1]), "+f"(d[2]), "+f"(d[3])
        : "r"(a[0]), "r"(a[1]), "r"(a[2]), "r"(a[3]), "r"(b0), "r"(b1));
}
// XOR swizzle inside a 128B row: 16B chunk index XORed with (row&7)
__device__ __forceinline__ uint32_t swz_off(int row, int byte_in_row) {
    return (uint32_t)(row * 128 + (byte_in_row ^ ((row & 7) << 4)));
}

// ---------------------------------------------------------------------------
// k_wimg: W -> bf16 hi/lo images (runs BEFORE any GEMM; 64 blocks)
// ---------------------------------------------------------------------------
__global__ void k_wimg(const float* __restrict__ W1l, const float* __restrict__ W1r,
                       const float* __restrict__ W2l, const float* __restrict__ W2r,
                       const float* __restrict__ W3l, const float* __restrict__ W3r) {
    int tid = blockIdx.x * 256 + threadIdx.x;   // 0..16383
    int img = tid >> 12, idx = tid & 4095;
    int n = idx >> 5, kp = idx & 31;
    int k0 = 2 * kp, k1 = k0 + 1;
    float v0, v1;
    if (img == 0) {
        v0 = (n < 64) ? W1l[k0 * 64 + n] : W1r[k0 * 64 + n - 64];
        v1 = (n < 64) ? W1l[k1 * 64 + n] : W1r[k1 * 64 + n - 64];
    } else if (img == 1) {
        v0 = (n < 64) ? W2l[k0 * 64 + n] : W2r[k0 * 64 + n - 64];
        v1 = (n < 64) ? W2l[k1 * 64 + n] : W2r[k1 * 64 + n - 64];
    } else if (img == 2) {
        v0 = W3l[k0 * 128 + n];
        v1 = W3l[k1 * 128 + n];
    } else {
        v0 = W3r[k0 * 128 + n];
        v1 = W3r[k1 * 128 + n];
    }
    uint16_t h0, l0, h1, l1;
    bf16_split(v0, h0, l0);
    bf16_split(v1, h1, l1);
    uint32_t off = swz_off(n, kp * 4);
    *(uint32_t*)(g_wimg_hi[img] + off) = (uint32_t)h0 | ((uint32_t)h1 << 16);
    *(uint32_t*)(g_wimg_lo[img] + off) = (uint32_t)l0 | ((uint32_t)l1 << 16);
}

// ---------------------------------------------------------------------------
// HMMA GEMM (layers 1/2): Y[128x128] = X @ [Wl|Wr], 3-term bf16 split.
// PRE=false: convert fp32 X in-kernel; extra blocks run the BUCKET SCATTER
//            (needs only g_cnt zero-at-entry; independent of GEMM data).
// PRE=true : A loaded from pre-split global bf16 hi/lo images (uint4 copy).
// Epilogue: cols<64 -> fp16 xl, cols>=64 -> fp32 xr.
// ---------------------------------------------------------------------------
#define SMA_HI 0
#define SMA_LO 16384
#define SMB_HI 32768
#define SMB_LO 49152
#define SM_TOT 65536

template <bool PRE>
__global__ void __launch_bounds__(256, 2) k_mma(const float* __restrict__ X,
                                                const unsigned char* __restrict__ Ahi,
                                                const unsigned char* __restrict__ Alo,
                                                const unsigned char* __restrict__ Bhi,
                                                const unsigned char* __restrict__ Blo,
                                                __half2* __restrict__ Y0h,
                                                float* __restrict__ Y1, int N,
                                                const int* __restrict__ ei, int E, int GB) {
    if (!PRE && blockIdx.x >= (unsigned)GB) {
        // bucket scatter side-grid
        for (int i = (blockIdx.x - GB) * 256 + threadIdx.x; i < E; i += 1024 * 256) {
            int d = ei[E + i];
            int p = atomicAdd(&g_cnt[d], 1);
            if (p < BCAP) g_bucket[d * BCAP + p] = ei[i];
        }
        return;
    }
    extern __shared__ char smem[];
    const uint32_t sb = smem_u32(smem);
    const int tid = threadIdx.x, wid = tid >> 5, lane = tid & 31;
    const int rowbase = blockIdx.x * 128;

    const uint4* bh = (const uint4*)Bhi;
    const uint4* bl = (const uint4*)Blo;
#pragma unroll
    for (int i = tid; i < 1024; i += 256) {
        ((uint4*)(smem + SMB_HI))[i] = bh[i];
        ((uint4*)(smem + SMB_LO))[i] = bl[i];
    }
    if (PRE) {
        const uint4* ah = (const uint4*)(Ahi + (size_t)rowbase * 128);
        const uint4* al = (const uint4*)(Alo + (size_t)rowbase * 128);
#pragma unroll
        for (int i = tid; i < 1024; i += 256) {
            ((uint4*)(smem + SMA_HI))[i] = ah[i];
            ((uint4*)(smem + SMA_LO))[i] = al[i];
        }
    } else {
#pragma unroll
        for (int i = tid; i < 4096; i += 256) {
            int r = i >> 5, kp = i & 31;
            int row = rowbase + r;
            float2 v = (row < N) ? *(const float2*)&X[row * 64 + 2 * kp]
                                 : make_float2(0.f, 0.f);
            uint16_t h0, l0, h1, l1;
            bf16_split(v.x, h0, l0);
            bf16_split(v.y, h1, l1);
            uint32_t off = swz_off(r, kp * 4);
            *(uint32_t*)(smem + SMA_HI + off) = (uint32_t)h0 | ((uint32_t)h1 << 16);
            *(uint32_t*)(smem + SMA_LO + off) = (uint32_t)l0 | ((uint32_t)l1 << 16);
        }
    }
    __syncthreads();

    const int m0 = (wid & 3) * 32;
    const int n0 = (wid >> 2) * 64;
    const int rl  = lane & 7;
    const int grp = lane >> 3;

    float acc[2][8][4];
#pragma unroll
    for (int mt = 0; mt < 2; mt++)
#pragma unroll
        for (int nt = 0; nt < 8; nt++)
#pragma unroll
            for (int j = 0; j < 4; j++) acc[mt][nt][j] = 0.f;

#pragma unroll
    for (int ks = 0; ks < 4; ks++) {
        const int cb = ks * 32;
        uint32_t ahi[2][4], alo[2][4];
#pragma unroll
        for (int mt = 0; mt < 2; mt++) {
            int arow = m0 + mt * 16 + (grp & 1) * 8 + rl;
            int abyte = cb + (grp >> 1) * 16;
            ldm_x4(ahi[mt], sb + SMA_HI + swz_off(arow, abyte));
            ldm_x4(alo[mt], sb + SMA_LO + swz_off(arow, abyte));
        }
#pragma unroll
        for (int np = 0; np < 4; np++) {
            int brow = n0 + np * 16 + (grp >> 1) * 8 + rl;
            int bbyte = cb + (grp & 1) * 16;
            uint32_t bhi[4], blo[4];
            ldm_x4(bhi, sb + SMB_HI + swz_off(brow, bbyte));
            ldm_x4(blo, sb + SMB_LO + swz_off(brow, bbyte));
            mma_bf16(acc[0][2 * np],     ahi[0], bhi[0], bhi[1]);
            mma_bf16(acc[1][2 * np],     ahi[1], bhi[0], bhi[1]);
            mma_bf16(acc[0][2 * np + 1], ahi[0], bhi[2], bhi[3]);
            mma_bf16(acc[1][2 * np + 1], ahi[1], bhi[2], bhi[3]);
            mma_bf16(acc[0][2 * np],     alo[0], bhi[0], bhi[1]);
            mma_bf16(acc[1][2 * np],     alo[1], bhi[0], bhi[1]);
            mma_bf16(acc[0][2 * np + 1], alo[0], bhi[2], bhi[3]);
            mma_bf16(acc[1][2 * np + 1], alo[1], bhi[2], bhi[3]);
            mma_bf16(acc[0][2 * np],     ahi[0], blo[0], blo[1]);
            mma_bf16(acc[1][2 * np],     ahi[1], blo[0], blo[1]);
            mma_bf16(acc[0][2 * np + 1], ahi[0], blo[2], blo[3]);
            mma_bf16(acc[1][2 * np + 1], ahi[1], blo[2], blo[3]);
        }
    }

    const int qr = lane >> 2, qc = (lane & 3) * 2;
#pragma unroll
    for (int mt = 0; mt < 2; mt++) {
#pragma unroll
        for (int nt = 0; nt < 8; nt++) {
            int col = n0 + nt * 8 + qc;
            int row0 = rowbase + m0 + mt * 16 + qr;
#pragma unroll
            for (int h = 0; h < 2; h++) {
                int row = row0 + h * 8;
                if (row < N) {
                    float vx = acc[mt][nt][2 * h], vy = acc[mt][nt][2 * h + 1];
                    if (col < 64) Y0h[row * 32 + (col >> 1)] = __floats2half2_rn(vx, vy);
                    else          *(float2*)&Y1[row * 64 + col - 64] = make_float2(vx, vy);
                }
            }
        }
    }
}

// ---------------------------------------------------------------------------
// Layer-3 fused GEMM: Y[128 x 256] = H @ [W3l | W3r], H from pre-split images.
// ---------------------------------------------------------------------------
#define SM3_AHI 0
#define SM3_ALO 16384
#define SM3_BHI 32768
#define SM3_BLO 65536
#define SM3_TOT 98304

__global__ void __launch_bounds__(512) k_mma3(const unsigned char* __restrict__ Ahi,
                                              const unsigned char* __restrict__ Alo,
                                              const unsigned char* __restrict__ Bhi2,
                                              const unsigned char* __restrict__ Blo2,
                                              const unsigned char* __restrict__ Bhi3,
                                              const unsigned char* __restrict__ Blo3,
                                              __half2* __restrict__ Y0h,
                                              float* __restrict__ Y1, int N) {
    extern __shared__ char smem[];
    const uint32_t sb = smem_u32(smem);
    const int tid = threadIdx.x, wid = tid >> 5, lane = tid & 31;
    const int rowbase = blockIdx.x * 128;

#pragma unroll
    for (int i = tid; i < 2048; i += 512) {
        ((uint4*)(smem + SM3_BHI))[i] = (i < 1024) ? ((const uint4*)Bhi2)[i]
                                                   : ((const uint4*)Bhi3)[i - 1024];
        ((uint4*)(smem + SM3_BLO))[i] = (i < 1024) ? ((const uint4*)Blo2)[i]
                                                   : ((const uint4*)Blo3)[i - 1024];
    }
    {
        const uint4* ah = (const uint4*)(Ahi + (size_t)rowbase * 128);
        const uint4* al = (const uint4*)(Alo + (size_t)rowbase * 128);
#pragma unroll
        for (int i = tid; i < 1024; i += 512) {
            ((uint4*)(smem + SM3_AHI))[i] = ah[i];
            ((uint4*)(smem + SM3_ALO))[i] = al[i];
        }
    }
    __syncthreads();

    const int m0 = (wid & 3) * 32;
    const int n0 = (wid >> 2) * 64;  // 0,64,128,192
    const int rl  = lane & 7;
    const int grp = lane >> 3;

    float acc[2][8][4];
#pragma unroll
    for (int mt = 0; mt < 2; mt++)
#pragma unroll
        for (int nt = 0; nt < 8; nt++)
#pragma unroll
            for (int j = 0; j < 4; j++) acc[mt][nt][j] = 0.f;

#pragma unroll
    for (int ks = 0; ks < 4; ks++) {
        const int cb = ks * 32;
        uint32_t ahi[2][4], alo[2][4];
#pragma unroll
        for (int mt = 0; mt < 2; mt++) {
            int arow = m0 + mt * 16 + (grp & 1) * 8 + rl;
            int abyte = cb + (grp >> 1) * 16;
            ldm_x4(ahi[mt], sb + SM3_AHI + swz_off(arow, abyte));
            ldm_x4(alo[mt], sb + SM3_ALO + swz_off(arow, abyte));
        }
#pragma unroll
        for (int np = 0; np < 4; np++) {
            int brow = n0 + np * 16 + (grp >> 1) * 8 + rl;
            int bbyte = cb + (grp & 1) * 16;
            uint32_t bhi[4], blo[4];
            ldm_x4(bhi, sb + SM3_BHI + swz_off(brow, bbyte));
            ldm_x4(blo, sb + SM3_BLO + swz_off(brow, bbyte));
            mma_bf16(acc[0][2 * np],     ahi[0], bhi[0], bhi[1]);
            mma_bf16(acc[1][2 * np],     ahi[1], bhi[0], bhi[1]);
            mma_bf16(acc[0][2 * np + 1], ahi[0], bhi[2], bhi[3]);
            mma_bf16(acc[1][2 * np + 1], ahi[1], bhi[2], bhi[3]);
            mma_bf16(acc[0][2 * np],     alo[0], bhi[0], bhi[1]);
            mma_bf16(acc[1][2 * np],     alo[1], bhi[0], bhi[1]);
            mma_bf16(acc[0][2 * np + 1], alo[0], bhi[2], bhi[3]);
            mma_bf16(acc[1][2 * np + 1], alo[1], bhi[2], bhi[3]);
            mma_bf16(acc[0][2 * np],     ahi[0], blo[0], blo[1]);
            mma_bf16(acc[1][2 * np],     ahi[1], blo[0], blo[1]);
            mma_bf16(acc[0][2 * np + 1], ahi[0], blo[2], blo[3]);
            mma_bf16(acc[1][2 * np + 1], ahi[1], blo[2], blo[3]);
        }
    }

    const int qr = lane >> 2, qc = (lane & 3) * 2;
#pragma unroll
    for (int mt = 0; mt < 2; mt++) {
#pragma unroll
        for (int nt = 0; nt < 8; nt++) {
            int col = n0 + nt * 8 + qc;
            int row0 = rowbase + m0 + mt * 16 + qr;
#pragma unroll
            for (int h = 0; h < 2; h++) {
                int row = row0 + h * 8;
                if (row < N) {
                    float vx = acc[mt][nt][2 * h], vy = acc[mt][nt][2 * h + 1];
                    if (col < 128) Y0h[row * 64 + (col >> 1)] = __floats2half2_rn(vx, vy);
                    else           *(float2*)&Y1[row * 128 + col - 128] = make_float2(vx, vy);
                }
            }
        }
    }
}

// ---------------------------------------------------------------------------
// Edge phase (half2 score + half2 quad partial sums; fp32 softmax state;
// bucketed adjacency with int4 loads + unconditional prefetch)
// ---------------------------------------------------------------------------
__device__ __forceinline__ float red8(float p) {
    p += __shfl_xor_sync(0xffffffffu, p, 4);
    p += __shfl_xor_sync(0xffffffffu, p, 2);
    p += __shfl_xor_sync(0xffffffffu, p, 1);
    return p;
}
__device__ __forceinline__ float red4(float p) {
    p += __shfl_xor_sync(0xffffffffu, p, 2);
    p += __shfl_xor_sync(0xffffffffu, p, 1);
    return p;
}

// half2 score: a*leaky(v+xr) summed over the lane's 4 features
__device__ __forceinline__ float hscore(__half2 vh0, __half2 vh1,
                                        __half2 xrh0, __half2 xrh1,
                                        __half2 ah0, __half2 ah1, __half2 c02) {
    __half2 t0 = __hadd2(vh0, xrh0);
    __half2 t1 = __hadd2(vh1, xrh1);
    t0 = __hmax2(t0, __hmul2(t0, c02));
    t1 = __hmax2(t1, __hmul2(t1, c02));
    __half2 s2 = __hfma2(ah1, t1, __hmul2(ah0, t0));
    return __half2float(__hadd(__low2half(s2), __high2half(s2)));
}

// k_edge64: two nodes per warp (16 lanes each, 4 fp16 feats/lane)
__global__ void k_edge64(const __half2* __restrict__ XLH, const float* __restrict__ XR,
                         const float* __restrict__ att, const float* __restrict__ bias,
                         uint2* __restrict__ OHI, uint2* __restrict__ OLO, int N) {
    const int lane = threadIdx.x & 31;
    const int hl   = lane & 15;
    const int wg   = (blockIdx.x * blockDim.x + threadIdx.x) >> 5;
    const int n    = wg * 2 + (lane >> 4);
    const bool valid = n < N;
    const int nc = valid ? n : N - 1;

    const uint2* XL2 = (const uint2*)XLH;
    const __half2 c02 = __float2half2_rn(0.2f);

    float4 a  = *(const float4*)&att[4 * hl];
    __half2 ah0 = __floats2half2_rn(a.x, a.y), ah1 = __floats2half2_rn(a.z, a.w);
    float4 xr = *(const float4*)&XR[nc * 64 + 4 * hl];
    __half2 xrh0 = __floats2half2_rn(xr.x, xr.y), xrh1 = __floats2half2_rn(xr.z, xr.w);

    uint2 su = XL2[nc * 16 + hl];
    __half2 svh0 = *(__half2*)&su.x, svh1 = *(__half2*)&su.y;
    float2 sf0 = __half22float2(svh0), sf1 = __half22float2(svh1);
    float4 acc = make_float4(sf0.x, sf0.y, sf1.x, sf1.y);

    float m = red4(hscore(svh0, svh1, xrh0, xrh1, ah0, ah1, c02));
    float d = 1.f;

    int deg  = valid ? g_cnt[nc] : 0;
    int odeg = __shfl_xor_sync(0xffffffffu, deg, 16);
    int nq = (max(deg, odeg) + 3) >> 2;

    const int base = nc * BCAP;
    int j = 0;
    int4 s4 = *(const int4*)&g_bucket[base];

    for (int q = 0; q < nq; q++) {
        uint2 u0 = XL2[s4.x * 16 + hl];
        uint2 u1 = XL2[s4.y * 16 + hl];
        uint2 u2 = XL2[s4.z * 16 + hl];
        uint2 u3 = XL2[s4.w * 16 + hl];
        int rem = deg - j;
        j += 4;
        s4 = *(const int4*)&g_bucket[base + j];

        __half2 v0h0 = *(__half2*)&u0.x, v0h1 = *(__half2*)&u0.y;
        __half2 v1h0 = *(__half2*)&u1.x, v1h1 = *(__half2*)&u1.y;
        __half2 v2h0 = *(__half2*)&u2.x, v2h1 = *(__half2*)&u2.y;
        __half2 v3h0 = *(__half2*)&u3.x, v3h1 = *(__half2*)&u3.y;

        float p0 = red4(hscore(v0h0, v0h1, xrh0, xrh1, ah0, ah1, c02));
        float p1 = red4(hscore(v1h0, v1h1, xrh0, xrh1, ah0, ah1, c02));
        float p2 = red4(hscore(v2h0, v2h1, xrh0, xrh1, ah0, ah1, c02));
        float p3 = red4(hscore(v3h0, v3h1, xrh0, xrh1, ah0, ah1, c02));
        p0 = (0 < rem) ? p0 : -1e30f;
        p1 = (1 < rem) ? p1 : -1e30f;
        p2 = (2 < rem) ? p2 : -1e30f;
        p3 = (3 < rem) ? p3 : -1e30f;

        float mq = fmaxf(fmaxf(p0, p1), fmaxf(p2, p3));
        float mn = fmaxf(m, mq);
        float w  = __expf(m - mn);
        float e0 = __expf(p0 - mn), e1 = __expf(p1 - mn);
        float e2 = __expf(p2 - mn), e3 = __expf(p3 - mn);

        __half2 eh0 = __float2half2_rn(e0), eh1 = __float2half2_rn(e1);
        __half2 eh2 = __float2half2_rn(e2), eh3 = __float2half2_rn(e3);
        __half2 sum0 = __hmul2(eh0, v0h0);
        sum0 = __hfma2(eh1, v1h0, sum0);
        sum0 = __hfma2(eh2, v2h0, sum0);
        sum0 = __hfma2(eh3, v3h0, sum0);
        __half2 sum1 = __hmul2(eh0, v0h1);
        sum1 = __hfma2(eh1, v1h1, sum1);
        sum1 = __hfma2(eh2, v2h1, sum1);
        sum1 = __hfma2(eh3, v3h1, sum1);
        float2 g0 = __half22float2(sum0), g1 = __half22float2(sum1);
        acc.x = acc.x * w + g0.x;
        acc.y = acc.y * w + g0.y;
        acc.z = acc.z * w + g1.x;
        acc.w = acc.w * w + g1.y;
        d = d * w + ((e0 + e1) + (e2 + e3));
        m = mn;
    }
    float inv = 1.f / d;
    float o0 = acc.x * inv + bias[4 * hl + 0];
    float o1 = acc.y * inv + bias[4 * hl + 1];
    float o2 = acc.z * inv + bias[4 * hl + 2];
    float o3 = acc.w * inv + bias[4 * hl + 3];
    o0 = o0 > 0.f ? o0 : (__expf(o0) - 1.f);
    o1 = o1 > 0.f ? o1 : (__expf(o1) - 1.f);
    o2 = o2 > 0.f ? o2 : (__expf(o2) - 1.f);
    o3 = o3 > 0.f ? o3 : (__expf(o3) - 1.f);
    if (valid) {
        uint16_t h0, l0, h1, l1, h2, l2, h3, l3;
        bf16_split(o0, h0, l0);
        bf16_split(o1, h1, l1);
        bf16_split(o2, h2, l2);
        bf16_split(o3, h3, l3);
        int idx = n * 16 + (hl ^ ((n & 7) << 1));   // swizzled 8B-unit offset
        OHI[idx] = make_uint2((uint32_t)h0 | ((uint32_t)h1 << 16),
                              (uint32_t)h2 | ((uint32_t)h3 << 16));
        OLO[idx] = make_uint2((uint32_t)l0 | ((uint32_t)l1 << 16),
                              (uint32_t)l2 | ((uint32_t)l3 << 16));
    }
}

// k_edge128_mean: one node per warp; also re-zeroes g_cnt for next replay.
__global__ void k_edge128_mean(const __half2* __restrict__ XLH, const float* __restrict__ XR,
                               const float* __restrict__ att, const float* __restrict__ bias,
                               float* __restrict__ OUT, int N) {
    int lane = threadIdx.x & 31;
    int n    = (blockIdx.x * blockDim.x + threadIdx.x) >> 5;
    if (n >= N) return;

    const __half2 c02 = __float2half2_rn(0.2f);
    float4 a  = *(const float4*)&att[4 * lane];
    __half2 ah0 = __floats2half2_rn(a.x, a.y), ah1 = __floats2half2_rn(a.z, a.w);
    float4 xr = *(const float4*)&XR[n * 128 + 4 * lane];
    __half2 xrh0 = __floats2half2_rn(xr.x, xr.y), xrh1 = __floats2half2_rn(xr.z, xr.w);

    uint2 su = *(const uint2*)&XLH[n * 64 + 2 * lane];
    __half2 svh0 = *(__half2*)&su.x, svh1 = *(__half2*)&su.y;
    float2 sf0 = __half22float2(svh0), sf1 = __half22float2(svh1);
    float4 acc = make_float4(sf0.x, sf0.y, sf1.x, sf1.y);

    float m = red8(hscore(svh0, svh1, xrh0, xrh1, ah0, ah1, c02));
    float d = 1.f;

    int deg = g_cnt[n];
    if (lane == 0) g_cnt[n] = 0;    // re-zero for next replay (last consumer)
    int nq = (deg + 3) >> 2;
    const int base = n * BCAP;
    int j = 0;
    int4 s4 = *(const int4*)&g_bucket[base];

    for (int q = 0; q < nq; q++) {
        uint2 u0 = *(const uint2*)&XLH[s4.x * 64 + 2 * lane];
        uint2 u1 = *(const uint2*)&XLH[s4.y * 64 + 2 * lane];
        uint2 u2 = *(const uint2*)&XLH[s4.z * 64 + 2 * lane];
        uint2 u3 = *(const uint2*)&XLH[s4.w * 64 + 2 * lane];
        int rem = deg - j;
        j += 4;
        s4 = *(const int4*)&g_bucket[base + j];

        __half2 v0h0 = *(__half2*)&u0.x, v0h1 = *(__half2*)&u0.y;
        __half2 v1h0 = *(__half2*)&u1.x, v1h1 = *(__half2*)&u1.y;
        __half2 v2h0 = *(__half2*)&u2.x, v2h1 = *(__half2*)&u2.y;
        __half2 v3h0 = *(__half2*)&u3.x, v3h1 = *(__half2*)&u3.y;

        float p0 = red8(hscore(v0h0, v0h1, xrh0, xrh1, ah0, ah1, c02));
        float p1 = red8(hscore(v1h0, v1h1, xrh0, xrh1, ah0, ah1, c02));
        float p2 = red8(hscore(v2h0, v2h1, xrh0, xrh1, ah0, ah1, c02));
        float p3 = red8(hscore(v3h0, v3h1, xrh0, xrh1, ah0, ah1, c02));
        p0 = (0 < rem) ? p0 : -1e30f;
        p1 = (1 < rem) ? p1 : -1e30f;
        p2 = (2 < rem) ? p2 : -1e30f;
        p3 = (3 < rem) ? p3 : -1e30f;

        float mq = fmaxf(fmaxf(p0, p1), fmaxf(p2, p3));
        float mn = fmaxf(m, mq);
        float w  = __expf(m - mn);
        float e0 = __expf(p0 - mn), e1 = __expf(p1 - mn);
        float e2 = __expf(p2 - mn), e3 = __expf(p3 - mn);

        __half2 eh0 = __float2half2_rn(e0), eh1 = __float2half2_rn(e1);
        __half2 eh2 = __float2half2_rn(e2), eh3 = __float2half2_rn(e3);
        __half2 sum0 = __hmul2(eh0, v0h0);
        sum0 = __hfma2(eh1, v1h0, sum0);
        sum0 = __hfma2(eh2, v2h0, sum0);
        sum0 = __hfma2(eh3, v3h0, sum0);
        __half2 sum1 = __hmul2(eh0, v0h1);
        sum1 = __hfma2(eh1, v1h1, sum1);
        sum1 = __hfma2(eh2, v2h1, sum1);
        sum1 = __hfma2(eh3, v3h1, sum1);
        float2 g0 = __half22float2(sum0), g1 = __half22float2(sum1);
        acc.x = acc.x * w + g0.x;
        acc.y = acc.y * w + g0.y;
        acc.z = acc.z * w + g1.x;
        acc.w = acc.w * w + g1.y;
        d = d * w + ((e0 + e1) + (e2 + e3));
        m = mn;
    }
    float inv = 1.f / d;
    float o0 = acc.x * inv, o1 = acc.y * inv, o2 = acc.z * inv, o3 = acc.w * inv;
#pragma unroll
    for (int off = 8; off <= 16; off <<= 1) {
        o0 += __shfl_xor_sync(0xffffffffu, o0, off);
        o1 += __shfl_xor_sync(0xffffffffu, o1, off);
        o2 += __shfl_xor_sync(0xffffffffu, o2, off);
        o3 += __shfl_xor_sync(0xffffffffu, o3, off);
    }
    if (lane < 8) {
        int c = 4 * lane;
        float4 o = make_float4(0.25f * o0 + bias[c + 0],
                               0.25f * o1 + bias[c + 1],
                               0.25f * o2 + bias[c + 2],
                               0.25f * o3 + bias[c + 3]);
        *(float4*)&OUT[n * 32 + c] = o;
    }
}

// ---------------------------------------------------------------------------
// Launch: k_wimg -> [GEMM1 ‖ bucket-scatter] -> edges/GEMMs (7 launches)
// ---------------------------------------------------------------------------
extern "C" void kernel_launch(void* const* d_in, const int* in_sizes, int n_in,
                              void* d_out, int out_size) {
    const float* x   = (const float*)d_in[0];
    const int*   ei  = (const int*)  d_in[1];
    const float* W1l = (const float*)d_in[2];
    const float* W1r = (const float*)d_in[3];
    const float* a1  = (const float*)d_in[4];
    const float* b1  = (const float*)d_in[5];
    const float* W2l = (const float*)d_in[6];
    const float* W2r = (const float*)d_in[7];
    const float* a2  = (const float*)d_in[8];
    const float* b2  = (const float*)d_in[9];
    const float* W3l = (const float*)d_in[10];
    const float* W3r = (const float*)d_in[11];
    const float* a3  = (const float*)d_in[12];
    const float* b3  = (const float*)d_in[13];
    float* out = (float*)d_out;

    const int N = in_sizes[0] / 64;
    const int E = in_sizes[1] / 2;

    float *xlf, *xr;
    unsigned char *hhi, *hlo;
    unsigned char (*whi)[16384], (*wlo)[16384];
    cudaGetSymbolAddress((void**)&xlf, g_xl);
    cudaGetSymbolAddress((void**)&xr,  g_xr);
    cudaGetSymbolAddress((void**)&hhi, g_hhi);
    cudaGetSymbolAddress((void**)&hlo, g_hlo);
    cudaGetSymbolAddress((void**)&whi, g_wimg_hi);
    cudaGetSymbolAddress((void**)&wlo, g_wimg_lo);
    __half2* xlh = (__half2*)xlf;

    cudaFuncSetAttribute(k_mma<false>, cudaFuncAttributeMaxDynamicSharedMemorySize, SM_TOT);
    cudaFuncSetAttribute(k_mma<true>,  cudaFuncAttributeMaxDynamicSharedMemorySize, SM_TOT);
    cudaFuncSetAttribute(k_mma3, cudaFuncAttributeMaxDynamicSharedMemorySize, SM3_TOT);

    const int GT  = (N + 127) / 128;
    const int EB  = (N + 15) / 16;    // edge64: 8 warps x 2 nodes per block
    const int EBM = (N + 7) / 8;      // edge128: 8 warps x 1 node per block

    // 0: W images (producer strictly before GEMM consumers)
    k_wimg<<<64, 256>>>(W1l, W1r, W2l, W2r, W3l, W3r);
    // 1: layer-1 GEMM + bucket-scatter side-grid (cnt zero-at-entry invariant)
    k_mma<false><<<GT + 1024, 256, SM_TOT>>>(x, nullptr, nullptr, whi[0], wlo[0],
                                             xlh, xr, N, ei, E, GT);
    // 2: layer-1 edge -> pre-split h images
    k_edge64<<<EB, 256>>>(xlh, xr, a1, b1, (uint2*)hhi, (uint2*)hlo, N);
    // 3: layer-2 GEMM (pre-split A)
    k_mma<true><<<GT, 256, SM_TOT>>>(nullptr, hhi, hlo, whi[1], wlo[1],
                                     xlh, xr, N, nullptr, 0, GT);
    // 4: layer-2 edge
    k_edge64<<<EB, 256>>>(xlh, xr, a2, b2, (uint2*)hhi, (uint2*)hlo, N);
    // 5: layer-3 fused dual-N GEMM (pre-split A)
    k_mma3<<<GT, 512, SM3_TOT>>>(hhi, hlo, whi[2], wlo[2], whi[3], wlo[3], xlh, xr, N);
    // 6: layer-3 edge (mean over heads) -> final output; re-zeroes g_cnt
    k_edge128_mean<<<EBM, 256>>>(xlh, xr, a3, b3, out, N);
}